// round 14
// baseline (speedup 1.0000x reference)
#include <cuda_runtime.h>
#include <math.h>

#define NE 8
#define NC 1000
#define DFEAT 59
#define NH1 256
#define NH2 128
#define TPB 16            // tokens per block (MLP kernel)
#define LN2F 0.69314718055994530942f

__device__ __forceinline__ float clipf(float x) {
    return fminf(fmaxf(x, -100.0f), 100.0f);
}

__device__ __forceinline__ float warp_sum(float v) {
    #pragma unroll
    for (int o = 16; o; o >>= 1) v += __shfl_xor_sync(0xffffffffu, v, o);
    return v;
}

// packed f32x2 FMA (Blackwell): acc.lo += a.lo*b.lo; acc.hi += a.hi*b.hi
__device__ __forceinline__ void ffma2(unsigned long long& acc,
                                      unsigned long long a, unsigned long long b) {
    asm("fma.rn.f32x2 %0, %1, %2, %0;" : "+l"(acc) : "l"(a), "l"(b));
}
__device__ __forceinline__ unsigned long long pack2(float lo, float hi) {
    unsigned long long r;
    asm("mov.b64 %0, {%1, %2};" : "=l"(r) : "f"(lo), "f"(hi));
    return r;
}
__device__ __forceinline__ float2 unpack2(unsigned long long v) {
    float2 r;
    asm("mov.b64 {%0, %1}, %2;" : "=f"(r.x), "=f"(r.y) : "l"(v));
    return r;
}

union F4U2 { float4 f; ulonglong2 u; };

// ---------------------------------------------------------------------------
// Kernel 1: feature extraction (unchanged math; t_base for split launches).
// One block per token, 256 threads (8 warps).
// ---------------------------------------------------------------------------
__global__ __launch_bounds__(256) void feat_kernel(
    const float* __restrict__ post, float* __restrict__ outFeats, int t_base)
{
    __shared__ __align__(16) float s_mp[1024];
    __shared__ __align__(16) float s_lmp[1024];
    __shared__ float red[24];
    __shared__ float s_maxp[NE];
    __shared__ float s_glob[3];

    const int t    = blockIdx.x + t_base;
    const int tid  = threadIdx.x;
    const int lane = tid & 31;
    const int w    = tid >> 5;

    const float4* base = (const float4*)(post + (size_t)t * (NE * NC));

    float a_var = 0.0f, a_ment = 0.0f, a_mn2 = 0.0f;
    if (tid < 250) {
        float4 v = base[tid];
        float sx = v.x, sy = v.y, sz = v.z, sw = v.w;
        float qx = v.x * v.x, qy = v.y * v.y, qz = v.z * v.z, qw = v.w * v.w;
        #pragma unroll
        for (int e = 1; e < 8; e++) {
            v = base[e * 250 + tid];
            sx += v.x; sy += v.y; sz += v.z; sw += v.w;
            qx = fmaf(v.x, v.x, qx); qy = fmaf(v.y, v.y, qy);
            qz = fmaf(v.z, v.z, qz); qw = fmaf(v.w, v.w, qw);
        }
        float m[4] = {sx * 0.125f, sy * 0.125f, sz * 0.125f, sw * 0.125f};
        float q[4] = {qx, qy, qz, qw};
        float lm[4];
        #pragma unroll
        for (int j = 0; j < 4; j++) {
            lm[j] = __log2f(m[j] + 1e-8f);
            a_var += fmaf(-8.0f * m[j], m[j], q[j]) * (1.0f / 7.0f);
            a_ment = fmaf(m[j], lm[j], a_ment);
            a_mn2  = fmaf(m[j], m[j], a_mn2);
        }
        float4 m4; m4.x = m[0];  m4.y = m[1];  m4.z = m[2];  m4.w = m[3];
        float4 l4; l4.x = lm[0]; l4.y = lm[1]; l4.z = lm[2]; l4.w = lm[3];
        ((float4*)s_mp)[tid]  = m4;
        ((float4*)s_lmp)[tid] = l4;
    } else {
        float4 z = make_float4(0.f, 0.f, 0.f, 0.f);
        ((float4*)s_mp)[tid]  = z;
        ((float4*)s_lmp)[tid] = z;
    }
    a_var  = warp_sum(a_var);
    a_ment = warp_sum(a_ment);
    a_mn2  = warp_sum(a_mn2);
    if (lane == 0) { red[w] = a_var; red[8 + w] = a_ment; red[16 + w] = a_mn2; }
    __syncthreads();
    if (tid == 0) {
        float v = 0.0f, me = 0.0f, mn2 = 0.0f;
        #pragma unroll
        for (int i = 0; i < 8; i++) { v += red[i]; me += red[8 + i]; mn2 += red[16 + i]; }
        s_glob[0] = v; s_glob[1] = me; s_glob[2] = mn2;
    }
    __syncthreads();

    {
        const int e = w;
        const float4* prow = base + e * 250;
        unsigned long long splp = 0ull, an2 = 0ull, adot = 0ull, aklb = 0ull;
        float t_0 = -1e30f, t_1 = -1e30f, t_2 = -1e30f, t_3 = -1e30f, t_4 = -1e30f;

        #pragma unroll
        for (int k = 0; k < 8; k++) {
            const int q = lane + 32 * k;
            F4U2 pv;
            if (q < 250) pv.f = __ldg(prow + q);
            else         pv.f = make_float4(0.f, 0.f, 0.f, 0.f);
            F4U2 mv, lv;
            mv.u = ((const ulonglong2*)s_mp)[q];
            lv.u = ((const ulonglong2*)s_lmp)[q];

            float lp0 = __log2f(pv.f.x + 1e-8f);
            float lp1 = __log2f(pv.f.y + 1e-8f);
            float lp2 = __log2f(pv.f.z + 1e-8f);
            float lp3 = __log2f(pv.f.w + 1e-8f);
            unsigned long long lp01 = pack2(lp0, lp1);
            unsigned long long lp23 = pack2(lp2, lp3);

            ffma2(splp, pv.u.x, lp01);   ffma2(splp, pv.u.y, lp23);
            ffma2(an2,  pv.u.x, pv.u.x); ffma2(an2,  pv.u.y, pv.u.y);
            ffma2(adot, pv.u.x, mv.u.x); ffma2(adot, pv.u.y, mv.u.y);
            ffma2(aklb, pv.u.x, lv.u.x); ffma2(aklb, pv.u.y, lv.u.y);

            #define TOP5_INS(P) { \
                float c1 = fminf(t_0, (P)); t_0 = fmaxf(t_0, (P)); \
                float c2 = fminf(t_1, c1);  t_1 = fmaxf(t_1, c1); \
                float c3 = fminf(t_2, c2);  t_2 = fmaxf(t_2, c2); \
                float c4 = fminf(t_3, c3);  t_3 = fmaxf(t_3, c3); \
                t_4 = fmaxf(t_4, c4); }
            TOP5_INS(pv.f.x) TOP5_INS(pv.f.y) TOP5_INS(pv.f.z) TOP5_INS(pv.f.w)
            #undef TOP5_INS
        }

        float2 u;
        u = unpack2(splp); float s_plp = u.x + u.y;
        u = unpack2(an2);  float n2    = u.x + u.y;
        u = unpack2(adot); float dot   = u.x + u.y;
        u = unpack2(aklb); float klb   = u.x + u.y;
        s_plp = warp_sum(s_plp);
        n2    = warp_sum(n2);
        dot   = warp_sum(dot);
        klb   = warp_sum(klb);

        int k = 0;
        float tkl[5];
        #pragma unroll
        for (int r = 0; r < 5; r++) {
            float cand = (k == 0) ? t_0 : (k == 1) ? t_1 : (k == 2) ? t_2
                       : (k == 3) ? t_3 : (k == 4) ? t_4 : -1e30f;
            float best = cand;
            int bl = lane;
            #pragma unroll
            for (int o = 16; o; o >>= 1) {
                float ov = __shfl_xor_sync(0xffffffffu, best, o);
                int   ol = __shfl_xor_sync(0xffffffffu, bl, o);
                if (ov > best || (ov == best && ol < bl)) { best = ov; bl = ol; }
            }
            tkl[r] = best;
            if (lane == bl) k++;
        }

        if (lane == 0) {
            float tk0 = tkl[0], tk1 = tkl[1];
            float mass = tkl[0] + tkl[1] + tkl[2] + tkl[3] + tkl[4];
            float ent  = -LN2F * s_plp;
            float kl   = LN2F * (s_plp - klb);
            float pn   = fmaxf(sqrtf(n2), 1e-8f);
            float mn   = fmaxf(sqrtf(s_glob[2]), 1e-8f);
            float cosv = dot / (pn * mn);
            float* fr = outFeats + (size_t)t * DFEAT;
            fr[0 * 8 + e] = clipf(ent);
            fr[1 * 8 + e] = clipf(mass);
            fr[2 * 8 + e] = clipf(1.0f - mass);
            fr[3 * 8 + e] = clipf(tk0);
            fr[4 * 8 + e] = clipf(tk0 - tk1);
            fr[5 * 8 + e] = clipf(cosv);
            fr[6 * 8 + e] = clipf(kl);
            s_maxp[e] = tk0;
        }
    }
    __syncthreads();

    if (tid == 0) {
        float s = 0.0f;
        #pragma unroll
        for (int e = 0; e < NE; e++) s += s_maxp[e];
        float mean = s * 0.125f;
        float ss = 0.0f;
        #pragma unroll
        for (int e = 0; e < NE; e++) { float d = s_maxp[e] - mean; ss = fmaf(d, d, ss); }
        float stdm = sqrtf(ss * (1.0f / 7.0f));
        float* fr = outFeats + (size_t)t * DFEAT;
        fr[56] = clipf(-LN2F * s_glob[1]);
        fr[57] = clipf(s_glob[0] * (1.0f / NC));
        fr[58] = clipf(stdm);
    }
}

// ---------------------------------------------------------------------------
// Kernel 2: fused MLP v4. 16 tokens / block, 256 threads, warp owns 2 tokens.
// LN1 and LN2 entirely in registers (warp reductions); h2 never hits smem;
// h1 written to smem once, post-LN. smem 24.5 KB -> 4 blocks/SM (reg-capped).
// ---------------------------------------------------------------------------
__global__ __launch_bounds__(256, 4) void mlp_fused(
    const float* __restrict__ feats,
    const float* __restrict__ W1, const float* __restrict__ b1,
    const float* __restrict__ g1, const float* __restrict__ be1,
    const float* __restrict__ W2, const float* __restrict__ b2,
    const float* __restrict__ g2, const float* __restrict__ be2,
    const float* __restrict__ W3, const float* __restrict__ b3,
    float* __restrict__ weights, float* __restrict__ logits)
{
    __shared__ __align__(16) float sfT[60 * TPB];     // transposed feats [k][tok], 3.8 KB
    __shared__ __align__(16) float sh[TPB * 260];     // post-LN h1, 16.6 KB
    __shared__ float sW3[8 * NH2];                    // 4 KB, [e][k]
    __shared__ float sb3[8];

    const int t0   = blockIdx.x * TPB;
    const int tid  = threadIdx.x;
    const int lane = tid & 31;
    const int w    = tid >> 5;
    const int T0   = 2 * w;        // warp's tokens: T0, T0+1

    // stage transposed feats + W3(transposed) + b3
    {
        const float* src = feats + (size_t)t0 * DFEAT;
        for (int i = tid; i < TPB * DFEAT; i += 256) {
            int T = i / DFEAT, d = i - T * DFEAT;
            sfT[d * TPB + T] = src[i];
        }
        for (int i = tid; i < NH2 * 8; i += 256) {
            int k = i >> 3, e = i & 7;
            sW3[e * NH2 + k] = W3[i];
        }
        if (tid < 8) sb3[tid] = b3[tid];
    }
    __syncthreads();

    // ---- GEMM1 + LN1 + ReLU (LN in registers): lane -> cols lane*8..+7 ----
    {
        const int j0 = lane * 8;
        unsigned long long acc[2][4];
        #pragma unroll
        for (int a = 0; a < 2; a++)
            #pragma unroll
            for (int b = 0; b < 4; b++) acc[a][b] = 0ull;

        #pragma unroll 4
        for (int k = 0; k < DFEAT; k++) {
            F4U2 wa, wb;
            wa.f = *(const float4*)(W1 + k * NH1 + j0);
            wb.f = *(const float4*)(W1 + k * NH1 + j0 + 4);
            float2 fv = *(const float2*)(sfT + k * TPB + T0);   // broadcast LDS.64
            unsigned long long f0 = pack2(fv.x, fv.x);
            unsigned long long f1 = pack2(fv.y, fv.y);
            ffma2(acc[0][0], wa.u.x, f0); ffma2(acc[0][1], wa.u.y, f0);
            ffma2(acc[0][2], wb.u.x, f0); ffma2(acc[0][3], wb.u.y, f0);
            ffma2(acc[1][0], wa.u.x, f1); ffma2(acc[1][1], wa.u.y, f1);
            ffma2(acc[1][2], wb.u.x, f1); ffma2(acc[1][3], wb.u.y, f1);
        }

        float4 ba  = *(const float4*)(b1 + j0);
        float4 bb  = *(const float4*)(b1 + j0 + 4);
        float4 gg0 = *(const float4*)(g1 + j0);
        float4 gg1 = *(const float4*)(g1 + j0 + 4);
        float4 bb0 = *(const float4*)(be1 + j0);
        float4 bb1 = *(const float4*)(be1 + j0 + 4);

        #pragma unroll
        for (int a = 0; a < 2; a++) {
            float2 p0 = unpack2(acc[a][0]);
            float2 p1 = unpack2(acc[a][1]);
            float2 p2 = unpack2(acc[a][2]);
            float2 p3 = unpack2(acc[a][3]);
            float v[8];
            v[0] = p0.x + ba.x; v[1] = p0.y + ba.y;
            v[2] = p1.x + ba.z; v[3] = p1.y + ba.w;
            v[4] = p2.x + bb.x; v[5] = p2.y + bb.y;
            v[6] = p3.x + bb.z; v[7] = p3.y + bb.w;

            float s = v[0] + v[1] + v[2] + v[3] + v[4] + v[5] + v[6] + v[7];
            s = warp_sum(s);
            float mu = s * (1.0f / NH1);
            float vs = 0.0f;
            #pragma unroll
            for (int j = 0; j < 8; j++) { float d = v[j] - mu; vs = fmaf(d, d, vs); }
            vs = warp_sum(vs);
            float inv = rsqrtf(vs * (1.0f / NH1) + 1e-5f);

            float4 o0, o1;
            o0.x = fmaxf((v[0] - mu) * inv * gg0.x + bb0.x, 0.0f);
            o0.y = fmaxf((v[1] - mu) * inv * gg0.y + bb0.y, 0.0f);
            o0.z = fmaxf((v[2] - mu) * inv * gg0.z + bb0.z, 0.0f);
            o0.w = fmaxf((v[3] - mu) * inv * gg0.w + bb0.w, 0.0f);
            o1.x = fmaxf((v[4] - mu) * inv * gg1.x + bb1.x, 0.0f);
            o1.y = fmaxf((v[5] - mu) * inv * gg1.y + bb1.y, 0.0f);
            o1.z = fmaxf((v[6] - mu) * inv * gg1.z + bb1.z, 0.0f);
            o1.w = fmaxf((v[7] - mu) * inv * gg1.w + bb1.w, 0.0f);
            float* row = sh + (T0 + a) * 260;
            *(float4*)(row + j0)     = o0;
            *(float4*)(row + j0 + 4) = o1;
        }
    }
    __syncthreads();

    // ---- GEMM2 (k unrolled by 4) + LN2 + GEMM3 + softmax, all in registers --
    {
        const int j0 = lane * 4;
        unsigned long long acc[2][2];
        acc[0][0] = 0ull; acc[0][1] = 0ull;
        acc[1][0] = 0ull; acc[1][1] = 0ull;

        const float* r0 = sh + (T0 + 0) * 260;
        const float* r1 = sh + (T0 + 1) * 260;

        #pragma unroll 2
        for (int k = 0; k < NH1; k += 4) {
            float4 f0v = *(const float4*)(r0 + k);   // LDS.128
            float4 f1v = *(const float4*)(r1 + k);
            #pragma unroll
            for (int i = 0; i < 4; i++) {
                F4U2 w4;
                w4.f = *(const float4*)(W2 + (k + i) * NH2 + j0);
                float fa = (i == 0) ? f0v.x : (i == 1) ? f0v.y : (i == 2) ? f0v.z : f0v.w;
                float fb = (i == 0) ? f1v.x : (i == 1) ? f1v.y : (i == 2) ? f1v.z : f1v.w;
                unsigned long long p0 = pack2(fa, fa);
                unsigned long long p1 = pack2(fb, fb);
                ffma2(acc[0][0], w4.u.x, p0); ffma2(acc[0][1], w4.u.y, p0);
                ffma2(acc[1][0], w4.u.x, p1); ffma2(acc[1][1], w4.u.y, p1);
            }
        }

        float4 bb  = *(const float4*)(b2 + j0);
        float4 gg  = *(const float4*)(g2 + j0);
        float4 bbn = *(const float4*)(be2 + j0);

        #pragma unroll
        for (int a = 0; a < 2; a++) {
            float2 p0 = unpack2(acc[a][0]);
            float2 p1 = unpack2(acc[a][1]);
            float v0 = p0.x + bb.x, v1 = p0.y + bb.y;
            float v2 = p1.x + bb.z, v3 = p1.y + bb.w;

            float s = v0 + v1 + v2 + v3;
            s = warp_sum(s);
            float mu = s * (1.0f / NH2);
            float vs = 0.0f;
            vs = fmaf(v0 - mu, v0 - mu, vs); vs = fmaf(v1 - mu, v1 - mu, vs);
            vs = fmaf(v2 - mu, v2 - mu, vs); vs = fmaf(v3 - mu, v3 - mu, vs);
            vs = warp_sum(vs);
            float inv = rsqrtf(vs * (1.0f / NH2) + 1e-5f);

            float h0 = fmaxf((v0 - mu) * inv * gg.x + bbn.x, 0.0f);
            float h1 = fmaxf((v1 - mu) * inv * gg.y + bbn.y, 0.0f);
            float h2 = fmaxf((v2 - mu) * inv * gg.z + bbn.z, 0.0f);
            float h3 = fmaxf((v3 - mu) * inv * gg.w + bbn.w, 0.0f);

            float acc3[8];
            #pragma unroll
            for (int e = 0; e < 8; e++) {
                float4 w3v = *(const float4*)(sW3 + e * NH2 + j0);  // LDS.128
                float t = h0 * w3v.x;
                t = fmaf(h1, w3v.y, t);
                t = fmaf(h2, w3v.z, t);
                t = fmaf(h3, w3v.w, t);
                acc3[e] = warp_sum(t);
            }

            if (lane == 0) {
                int tg = t0 + T0 + a;
                float lg[8];
                float mx = -1e30f;
                #pragma unroll
                for (int e = 0; e < 8; e++) { lg[e] = acc3[e] + sb3[e]; mx = fmaxf(mx, lg[e]); }
                float ex[8];
                float ssum = 0.0f;
                #pragma unroll
                for (int e = 0; e < 8; e++) { ex[e] = __expf(lg[e] - mx); ssum += ex[e]; }
                float invs = 1.0f / ssum;
                float4* lgo = (float4*)(logits + (size_t)tg * 8);
                float4* wgo = (float4*)(weights + (size_t)tg * 8);
                float4 o;
                o.x = lg[0]; o.y = lg[1]; o.z = lg[2]; o.w = lg[3]; lgo[0] = o;
                o.x = lg[4]; o.y = lg[5]; o.z = lg[6]; o.w = lg[7]; lgo[1] = o;
                o.x = ex[0] * invs; o.y = ex[1] * invs; o.z = ex[2] * invs; o.w = ex[3] * invs; wgo[0] = o;
                o.x = ex[4] * invs; o.y = ex[5] * invs; o.z = ex[6] * invs; o.w = ex[7] * invs; wgo[1] = o;
            }
        }
    }
}

// ---------------------------------------------------------------------------
extern "C" void kernel_launch(void* const* d_in, const int* in_sizes, int n_in,
                              void* d_out, int out_size)
{
    const float* post = (const float*)d_in[0];
    const float* W1   = (const float*)d_in[1];
    const float* b1   = (const float*)d_in[2];
    const float* g1   = (const float*)d_in[3];
    const float* be1  = (const float*)d_in[4];
    const float* W2   = (const float*)d_in[5];
    const float* b2   = (const float*)d_in[6];
    const float* g2   = (const float*)d_in[7];
    const float* be2  = (const float*)d_in[8];
    const float* W3   = (const float*)d_in[9];
    const float* b3   = (const float*)d_in[10];

    const int B = in_sizes[0] / (NE * NC);

    float* out     = (float*)d_out;
    float* weights = out;                       // (B, 8)
    float* logits  = out + (size_t)B * 8;       // (B, 8)
    float* feats   = out + (size_t)B * 16;      // (B, 59)

    // feat split into 3 launches (same total work) so ncu -s 5 captures one.
    int n1 = (B + 2) / 3;
    int n2 = n1;
    int n3 = B - n1 - n2;
    feat_kernel<<<n1, 256>>>(post, feats, 0);
    feat_kernel<<<n2, 256>>>(post, feats, n1);
    feat_kernel<<<n3, 256>>>(post, feats, n1 + n2);
    mlp_fused<<<B / TPB, 256>>>(feats, W1, b1, g1, be1, W2, b2, g2, be2,
                                W3, b3, weights, logits);
}

// round 15
// speedup vs baseline: 1.1863x; 1.1863x over previous
#include <cuda_runtime.h>
#include <math.h>

#define NE 8
#define NC 1000
#define DFEAT 59
#define NH1 256
#define NH2 128
#define TPB 32            // tokens per block (MLP kernel)
#define LN2F 0.69314718055994530942f

__device__ __forceinline__ float clipf(float x) {
    return fminf(fmaxf(x, -100.0f), 100.0f);
}

__device__ __forceinline__ float warp_sum(float v) {
    #pragma unroll
    for (int o = 16; o; o >>= 1) v += __shfl_xor_sync(0xffffffffu, v, o);
    return v;
}

// packed f32x2 FMA (Blackwell): acc.lo += a.lo*b.lo; acc.hi += a.hi*b.hi
__device__ __forceinline__ void ffma2(unsigned long long& acc,
                                      unsigned long long a, unsigned long long b) {
    asm("fma.rn.f32x2 %0, %1, %2, %0;" : "+l"(acc) : "l"(a), "l"(b));
}
__device__ __forceinline__ unsigned long long pack2(float lo, float hi) {
    unsigned long long r;
    asm("mov.b64 %0, {%1, %2};" : "=l"(r) : "f"(lo), "f"(hi));
    return r;
}
__device__ __forceinline__ float2 unpack2(unsigned long long v) {
    float2 r;
    asm("mov.b64 {%0, %1}, %2;" : "=f"(r.x), "=f"(r.y) : "l"(v));
    return r;
}

union F4U2 { float4 f; ulonglong2 u; };

// ---------------------------------------------------------------------------
// Kernel 1: feature extraction (r10 version — known good, single launch).
// One block per token, 256 threads (8 warps).
// ---------------------------------------------------------------------------
__global__ __launch_bounds__(256) void feat_kernel(
    const float* __restrict__ post, float* __restrict__ outFeats)
{
    __shared__ __align__(16) float s_mp[1024];
    __shared__ __align__(16) float s_lmp[1024];
    __shared__ float red[24];
    __shared__ float s_maxp[NE];
    __shared__ float s_glob[3];

    const int t    = blockIdx.x;
    const int tid  = threadIdx.x;
    const int lane = tid & 31;
    const int w    = tid >> 5;

    const float4* base = (const float4*)(post + (size_t)t * (NE * NC));

    float a_var = 0.0f, a_ment = 0.0f, a_mn2 = 0.0f;
    if (tid < 250) {
        float4 v = base[tid];
        float sx = v.x, sy = v.y, sz = v.z, sw = v.w;
        float qx = v.x * v.x, qy = v.y * v.y, qz = v.z * v.z, qw = v.w * v.w;
        #pragma unroll
        for (int e = 1; e < 8; e++) {
            v = base[e * 250 + tid];
            sx += v.x; sy += v.y; sz += v.z; sw += v.w;
            qx = fmaf(v.x, v.x, qx); qy = fmaf(v.y, v.y, qy);
            qz = fmaf(v.z, v.z, qz); qw = fmaf(v.w, v.w, qw);
        }
        float m[4] = {sx * 0.125f, sy * 0.125f, sz * 0.125f, sw * 0.125f};
        float q[4] = {qx, qy, qz, qw};
        float lm[4];
        #pragma unroll
        for (int j = 0; j < 4; j++) {
            lm[j] = __log2f(m[j] + 1e-8f);
            a_var += fmaf(-8.0f * m[j], m[j], q[j]) * (1.0f / 7.0f);
            a_ment = fmaf(m[j], lm[j], a_ment);
            a_mn2  = fmaf(m[j], m[j], a_mn2);
        }
        float4 m4; m4.x = m[0];  m4.y = m[1];  m4.z = m[2];  m4.w = m[3];
        float4 l4; l4.x = lm[0]; l4.y = lm[1]; l4.z = lm[2]; l4.w = lm[3];
        ((float4*)s_mp)[tid]  = m4;
        ((float4*)s_lmp)[tid] = l4;
    } else {
        float4 z = make_float4(0.f, 0.f, 0.f, 0.f);
        ((float4*)s_mp)[tid]  = z;
        ((float4*)s_lmp)[tid] = z;
    }
    a_var  = warp_sum(a_var);
    a_ment = warp_sum(a_ment);
    a_mn2  = warp_sum(a_mn2);
    if (lane == 0) { red[w] = a_var; red[8 + w] = a_ment; red[16 + w] = a_mn2; }
    __syncthreads();
    if (tid == 0) {
        float v = 0.0f, me = 0.0f, mn2 = 0.0f;
        #pragma unroll
        for (int i = 0; i < 8; i++) { v += red[i]; me += red[8 + i]; mn2 += red[16 + i]; }
        s_glob[0] = v; s_glob[1] = me; s_glob[2] = mn2;
    }
    __syncthreads();

    {
        const int e = w;
        const float4* prow = base + e * 250;
        unsigned long long splp = 0ull, an2 = 0ull, adot = 0ull, aklb = 0ull;
        float t_0 = -1e30f, t_1 = -1e30f, t_2 = -1e30f, t_3 = -1e30f, t_4 = -1e30f;

        #pragma unroll
        for (int k = 0; k < 8; k++) {
            const int q = lane + 32 * k;
            F4U2 pv;
            if (q < 250) pv.f = __ldg(prow + q);
            else         pv.f = make_float4(0.f, 0.f, 0.f, 0.f);
            F4U2 mv, lv;
            mv.u = ((const ulonglong2*)s_mp)[q];
            lv.u = ((const ulonglong2*)s_lmp)[q];

            float lp0 = __log2f(pv.f.x + 1e-8f);
            float lp1 = __log2f(pv.f.y + 1e-8f);
            float lp2 = __log2f(pv.f.z + 1e-8f);
            float lp3 = __log2f(pv.f.w + 1e-8f);
            unsigned long long lp01 = pack2(lp0, lp1);
            unsigned long long lp23 = pack2(lp2, lp3);

            ffma2(splp, pv.u.x, lp01);   ffma2(splp, pv.u.y, lp23);
            ffma2(an2,  pv.u.x, pv.u.x); ffma2(an2,  pv.u.y, pv.u.y);
            ffma2(adot, pv.u.x, mv.u.x); ffma2(adot, pv.u.y, mv.u.y);
            ffma2(aklb, pv.u.x, lv.u.x); ffma2(aklb, pv.u.y, lv.u.y);

            #define TOP5_INS(P) { \
                float c1 = fminf(t_0, (P)); t_0 = fmaxf(t_0, (P)); \
                float c2 = fminf(t_1, c1);  t_1 = fmaxf(t_1, c1); \
                float c3 = fminf(t_2, c2);  t_2 = fmaxf(t_2, c2); \
                float c4 = fminf(t_3, c3);  t_3 = fmaxf(t_3, c3); \
                t_4 = fmaxf(t_4, c4); }
            TOP5_INS(pv.f.x) TOP5_INS(pv.f.y) TOP5_INS(pv.f.z) TOP5_INS(pv.f.w)
            #undef TOP5_INS
        }

        float2 u;
        u = unpack2(splp); float s_plp = u.x + u.y;
        u = unpack2(an2);  float n2    = u.x + u.y;
        u = unpack2(adot); float dot   = u.x + u.y;
        u = unpack2(aklb); float klb   = u.x + u.y;
        s_plp = warp_sum(s_plp);
        n2    = warp_sum(n2);
        dot   = warp_sum(dot);
        klb   = warp_sum(klb);

        int k = 0;
        float tkl[5];
        #pragma unroll
        for (int r = 0; r < 5; r++) {
            float cand = (k == 0) ? t_0 : (k == 1) ? t_1 : (k == 2) ? t_2
                       : (k == 3) ? t_3 : (k == 4) ? t_4 : -1e30f;
            float best = cand;
            int bl = lane;
            #pragma unroll
            for (int o = 16; o; o >>= 1) {
                float ov = __shfl_xor_sync(0xffffffffu, best, o);
                int   ol = __shfl_xor_sync(0xffffffffu, bl, o);
                if (ov > best || (ov == best && ol < bl)) { best = ov; bl = ol; }
            }
            tkl[r] = best;
            if (lane == bl) k++;
        }

        if (lane == 0) {
            float tk0 = tkl[0], tk1 = tkl[1];
            float mass = tkl[0] + tkl[1] + tkl[2] + tkl[3] + tkl[4];
            float ent  = -LN2F * s_plp;
            float kl   = LN2F * (s_plp - klb);
            float pn   = fmaxf(sqrtf(n2), 1e-8f);
            float mn   = fmaxf(sqrtf(s_glob[2]), 1e-8f);
            float cosv = dot / (pn * mn);
            float* fr = outFeats + (size_t)t * DFEAT;
            fr[0 * 8 + e] = clipf(ent);
            fr[1 * 8 + e] = clipf(mass);
            fr[2 * 8 + e] = clipf(1.0f - mass);
            fr[3 * 8 + e] = clipf(tk0);
            fr[4 * 8 + e] = clipf(tk0 - tk1);
            fr[5 * 8 + e] = clipf(cosv);
            fr[6 * 8 + e] = clipf(kl);
            s_maxp[e] = tk0;
        }
    }
    __syncthreads();

    if (tid == 0) {
        float s = 0.0f;
        #pragma unroll
        for (int e = 0; e < NE; e++) s += s_maxp[e];
        float mean = s * 0.125f;
        float ss = 0.0f;
        #pragma unroll
        for (int e = 0; e < NE; e++) { float d = s_maxp[e] - mean; ss = fmaf(d, d, ss); }
        float stdm = sqrtf(ss * (1.0f / 7.0f));
        float* fr = outFeats + (size_t)t * DFEAT;
        fr[56] = clipf(-LN2F * s_glob[1]);
        fr[57] = clipf(s_glob[0] * (1.0f / NC));
        fr[58] = clipf(stdm);
    }
}

// ---------------------------------------------------------------------------
// Kernel 2: fused MLP v5. TPB=32 (weight traffic amortized), warp owns 4
// tokens, LN1/LN2 in registers, h2 never in smem, h1 written once post-LN.
// smem 45 KB -> 4 blocks/SM (reg cap 64).
// ---------------------------------------------------------------------------
__global__ __launch_bounds__(256, 4) void mlp_fused(
    const float* __restrict__ feats,
    const float* __restrict__ W1, const float* __restrict__ b1,
    const float* __restrict__ g1, const float* __restrict__ be1,
    const float* __restrict__ W2, const float* __restrict__ b2,
    const float* __restrict__ g2, const float* __restrict__ be2,
    const float* __restrict__ W3, const float* __restrict__ b3,
    float* __restrict__ weights, float* __restrict__ logits)
{
    __shared__ __align__(16) float sfT[60 * TPB];     // transposed feats, 7.7 KB
    __shared__ __align__(16) float sh[TPB * 260];     // post-LN h1, 33.3 KB
    __shared__ float sW3[8 * NH2];                    // 4 KB, [e][k]
    __shared__ float sb3[8];

    const int t0   = blockIdx.x * TPB;
    const int tid  = threadIdx.x;
    const int lane = tid & 31;
    const int w    = tid >> 5;
    const int T0   = 4 * w;        // warp's tokens: T0..T0+3

    // stage transposed feats + W3(transposed) + b3
    {
        const float* src = feats + (size_t)t0 * DFEAT;
        for (int i = tid; i < TPB * DFEAT; i += 256) {
            int T = i / DFEAT, d = i - T * DFEAT;
            sfT[d * TPB + T] = src[i];
        }
        for (int i = tid; i < NH2 * 8; i += 256) {
            int k = i >> 3, e = i & 7;
            sW3[e * NH2 + k] = W3[i];
        }
        if (tid < 8) sb3[tid] = b3[tid];
    }
    __syncthreads();

    // ---- GEMM1 + LN1 + ReLU (LN in registers): lane -> cols lane*8..+7 ----
    {
        const int j0 = lane * 8;
        unsigned long long acc[4][4];   // [token][col-pair]
        #pragma unroll
        for (int a = 0; a < 4; a++)
            #pragma unroll
            for (int b = 0; b < 4; b++) acc[a][b] = 0ull;

        #pragma unroll 2
        for (int k = 0; k < DFEAT; k++) {
            F4U2 wa, wb;
            wa.f = *(const float4*)(W1 + k * NH1 + j0);
            wb.f = *(const float4*)(W1 + k * NH1 + j0 + 4);
            float4 fv = *(const float4*)(sfT + k * TPB + T0);   // broadcast LDS.128
            unsigned long long f0 = pack2(fv.x, fv.x);
            unsigned long long f1 = pack2(fv.y, fv.y);
            unsigned long long f2 = pack2(fv.z, fv.z);
            unsigned long long f3 = pack2(fv.w, fv.w);
            ffma2(acc[0][0], wa.u.x, f0); ffma2(acc[0][1], wa.u.y, f0);
            ffma2(acc[0][2], wb.u.x, f0); ffma2(acc[0][3], wb.u.y, f0);
            ffma2(acc[1][0], wa.u.x, f1); ffma2(acc[1][1], wa.u.y, f1);
            ffma2(acc[1][2], wb.u.x, f1); ffma2(acc[1][3], wb.u.y, f1);
            ffma2(acc[2][0], wa.u.x, f2); ffma2(acc[2][1], wa.u.y, f2);
            ffma2(acc[2][2], wb.u.x, f2); ffma2(acc[2][3], wb.u.y, f2);
            ffma2(acc[3][0], wa.u.x, f3); ffma2(acc[3][1], wa.u.y, f3);
            ffma2(acc[3][2], wb.u.x, f3); ffma2(acc[3][3], wb.u.y, f3);
        }

        float4 ba  = *(const float4*)(b1 + j0);
        float4 bb  = *(const float4*)(b1 + j0 + 4);
        float4 gg0 = *(const float4*)(g1 + j0);
        float4 gg1 = *(const float4*)(g1 + j0 + 4);
        float4 bb0 = *(const float4*)(be1 + j0);
        float4 bb1 = *(const float4*)(be1 + j0 + 4);

        #pragma unroll
        for (int a = 0; a < 4; a++) {
            float2 p0 = unpack2(acc[a][0]);
            float2 p1 = unpack2(acc[a][1]);
            float2 p2 = unpack2(acc[a][2]);
            float2 p3 = unpack2(acc[a][3]);
            float v[8];
            v[0] = p0.x + ba.x; v[1] = p0.y + ba.y;
            v[2] = p1.x + ba.z; v[3] = p1.y + ba.w;
            v[4] = p2.x + bb.x; v[5] = p2.y + bb.y;
            v[6] = p3.x + bb.z; v[7] = p3.y + bb.w;

            float s = v[0] + v[1] + v[2] + v[3] + v[4] + v[5] + v[6] + v[7];
            s = warp_sum(s);
            float mu = s * (1.0f / NH1);
            float vs = 0.0f;
            #pragma unroll
            for (int j = 0; j < 8; j++) { float d = v[j] - mu; vs = fmaf(d, d, vs); }
            vs = warp_sum(vs);
            float inv = rsqrtf(vs * (1.0f / NH1) + 1e-5f);

            float4 o0, o1;
            o0.x = fmaxf((v[0] - mu) * inv * gg0.x + bb0.x, 0.0f);
            o0.y = fmaxf((v[1] - mu) * inv * gg0.y + bb0.y, 0.0f);
            o0.z = fmaxf((v[2] - mu) * inv * gg0.z + bb0.z, 0.0f);
            o0.w = fmaxf((v[3] - mu) * inv * gg0.w + bb0.w, 0.0f);
            o1.x = fmaxf((v[4] - mu) * inv * gg1.x + bb1.x, 0.0f);
            o1.y = fmaxf((v[5] - mu) * inv * gg1.y + bb1.y, 0.0f);
            o1.z = fmaxf((v[6] - mu) * inv * gg1.z + bb1.z, 0.0f);
            o1.w = fmaxf((v[7] - mu) * inv * gg1.w + bb1.w, 0.0f);
            float* row = sh + (T0 + a) * 260;
            *(float4*)(row + j0)     = o0;
            *(float4*)(row + j0 + 4) = o1;
        }
    }
    __syncthreads();

    // ---- GEMM2 + LN2 + GEMM3 + softmax, all in registers ----
    {
        const int j0 = lane * 4;
        unsigned long long acc[4][2];   // [token][col-pair]
        #pragma unroll
        for (int a = 0; a < 4; a++) { acc[a][0] = 0ull; acc[a][1] = 0ull; }

        const float* r0 = sh + (T0 + 0) * 260;
        const float* r1 = sh + (T0 + 1) * 260;
        const float* r2 = sh + (T0 + 2) * 260;
        const float* r3 = sh + (T0 + 3) * 260;

        #pragma unroll 2
        for (int k = 0; k < NH1; k += 4) {
            float4 f0v = *(const float4*)(r0 + k);   // LDS.128
            float4 f1v = *(const float4*)(r1 + k);
            float4 f2v = *(const float4*)(r2 + k);
            float4 f3v = *(const float4*)(r3 + k);
            #pragma unroll
            for (int i = 0; i < 4; i++) {
                F4U2 w4;
                w4.f = *(const float4*)(W2 + (k + i) * NH2 + j0);
                float fa = (i == 0) ? f0v.x : (i == 1) ? f0v.y : (i == 2) ? f0v.z : f0v.w;
                float fb = (i == 0) ? f1v.x : (i == 1) ? f1v.y : (i == 2) ? f1v.z : f1v.w;
                float fc = (i == 0) ? f2v.x : (i == 1) ? f2v.y : (i == 2) ? f2v.z : f2v.w;
                float fd = (i == 0) ? f3v.x : (i == 1) ? f3v.y : (i == 2) ? f3v.z : f3v.w;
                unsigned long long p0 = pack2(fa, fa);
                unsigned long long p1 = pack2(fb, fb);
                unsigned long long p2 = pack2(fc, fc);
                unsigned long long p3 = pack2(fd, fd);
                ffma2(acc[0][0], w4.u.x, p0); ffma2(acc[0][1], w4.u.y, p0);
                ffma2(acc[1][0], w4.u.x, p1); ffma2(acc[1][1], w4.u.y, p1);
                ffma2(acc[2][0], w4.u.x, p2); ffma2(acc[2][1], w4.u.y, p2);
                ffma2(acc[3][0], w4.u.x, p3); ffma2(acc[3][1], w4.u.y, p3);
            }
        }

        float4 bb  = *(const float4*)(b2 + j0);
        float4 gg  = *(const float4*)(g2 + j0);
        float4 bbn = *(const float4*)(be2 + j0);

        #pragma unroll
        for (int a = 0; a < 4; a++) {
            float2 p0 = unpack2(acc[a][0]);
            float2 p1 = unpack2(acc[a][1]);
            float v0 = p0.x + bb.x, v1 = p0.y + bb.y;
            float v2 = p1.x + bb.z, v3 = p1.y + bb.w;

            float s = v0 + v1 + v2 + v3;
            s = warp_sum(s);
            float mu = s * (1.0f / NH2);
            float vs = 0.0f;
            vs = fmaf(v0 - mu, v0 - mu, vs); vs = fmaf(v1 - mu, v1 - mu, vs);
            vs = fmaf(v2 - mu, v2 - mu, vs); vs = fmaf(v3 - mu, v3 - mu, vs);
            vs = warp_sum(vs);
            float inv = rsqrtf(vs * (1.0f / NH2) + 1e-5f);

            float h0 = fmaxf((v0 - mu) * inv * gg.x + bbn.x, 0.0f);
            float h1 = fmaxf((v1 - mu) * inv * gg.y + bbn.y, 0.0f);
            float h2 = fmaxf((v2 - mu) * inv * gg.z + bbn.z, 0.0f);
            float h3 = fmaxf((v3 - mu) * inv * gg.w + bbn.w, 0.0f);

            float acc3[8];
            #pragma unroll
            for (int e = 0; e < 8; e++) {
                float4 w3v = *(const float4*)(sW3 + e * NH2 + j0);  // LDS.128
                float t = h0 * w3v.x;
                t = fmaf(h1, w3v.y, t);
                t = fmaf(h2, w3v.z, t);
                t = fmaf(h3, w3v.w, t);
                acc3[e] = warp_sum(t);
            }

            if (lane == 0) {
                int tg = t0 + T0 + a;
                float lg[8];
                float mx = -1e30f;
                #pragma unroll
                for (int e = 0; e < 8; e++) { lg[e] = acc3[e] + sb3[e]; mx = fmaxf(mx, lg[e]); }
                float ex[8];
                float ssum = 0.0f;
                #pragma unroll
                for (int e = 0; e < 8; e++) { ex[e] = __expf(lg[e] - mx); ssum += ex[e]; }
                float invs = 1.0f / ssum;
                float4* lgo = (float4*)(logits + (size_t)tg * 8);
                float4* wgo = (float4*)(weights + (size_t)tg * 8);
                float4 o;
                o.x = lg[0]; o.y = lg[1]; o.z = lg[2]; o.w = lg[3]; lgo[0] = o;
                o.x = lg[4]; o.y = lg[5]; o.z = lg[6]; o.w = lg[7]; lgo[1] = o;
                o.x = ex[0] * invs; o.y = ex[1] * invs; o.z = ex[2] * invs; o.w = ex[3] * invs; wgo[0] = o;
                o.x = ex[4] * invs; o.y = ex[5] * invs; o.z = ex[6] * invs; o.w = ex[7] * invs; wgo[1] = o;
            }
        }
    }
}

// ---------------------------------------------------------------------------
extern "C" void kernel_launch(void* const* d_in, const int* in_sizes, int n_in,
                              void* d_out, int out_size)
{
    const float* post = (const float*)d_in[0];
    const float* W1   = (const float*)d_in[1];
    const float* b1   = (const float*)d_in[2];
    const float* g1   = (const float*)d_in[3];
    const float* be1  = (const float*)d_in[4];
    const float* W2   = (const float*)d_in[5];
    const float* b2   = (const float*)d_in[6];
    const float* g2   = (const float*)d_in[7];
    const float* be2  = (const float*)d_in[8];
    const float* W3   = (const float*)d_in[9];
    const float* b3   = (const float*)d_in[10];

    const int B = in_sizes[0] / (NE * NC);

    float* out     = (float*)d_out;
    float* weights = out;                       // (B, 8)
    float* logits  = out + (size_t)B * 8;       // (B, 8)
    float* feats   = out + (size_t)B * 16;      // (B, 59)

    feat_kernel<<<B, 256>>>(post, feats);
    mlp_fused<<<B / TPB, 256>>>(feats, W1, b1, g1, be1, W2, b2, g2, be2,
                                W3, b3, weights, logits);
}